// round 12
// baseline (speedup 1.0000x reference)
#include <cuda_runtime.h>
#include <cuda_fp16.h>
#include <math.h>

#define BATCH 32
#define T     1024
#define DIM   64
#define NW    8                 // DP strips per batch (128 rows each)
#define NCH   76                // chunks of 16 steps: 1216 steps
#define SPAD  1248              // NCH*16 + 32 FIFO pad
#define HANDW 1220              // handoff row width (halves)
#define SRMAX 221               // epilogue s-rows per tile
#define NUNITS 252              // producer units: 84 CTAs * 3
#define NTILES 8192             // 32 b * 8 w * 32 jt
#define RSTR  1280              // global ring stride (halves) per batch
// DP CTA smem: hand 5 rows * HANDW halves + progress[4]
#define DP_PROG_OFF (5 * HANDW * 2)           // 12200
// producer unit: Ah[128][72]h | Bh[32][72]h | na[128]f | nb4[4*32]f
#define BH_OFF     18432
#define NA_OFF     23040
#define NB_OFF     23552
#define UNIT_BYTES 24064
#define SMEM_DYN   (3 * UNIT_BYTES)           // 72192

// fp16 cost^2, skew-slotted: g_cst[((b*NW+w)*SPAD + s)*128 + i] holds
// cost[128w+i][s - phi(i)], phi(i) = 6*(i>>2) + (i&3). Invalid = +INF.
__device__ __half g_cst[(size_t)BATCH * NW * SPAD * 128];
__device__ __align__(16) __half g_ring[BATCH * RSTR];   // w3->w4 handoff rows
__device__ int   g_xprog[BATCH];                        // w3->w4 progress
__device__ float g_dists[BATCH];
__device__ int   g_flag[BATCH * NW * 32];
__device__ unsigned char g_pairs[256];

__device__ __forceinline__ unsigned hmin2u(unsigned a, unsigned b) {
    __half2 r = __hmin2(*reinterpret_cast<__half2*>(&a), *reinterpret_cast<__half2*>(&b));
    return *reinterpret_cast<unsigned*>(&r);
}
__device__ __forceinline__ unsigned hmax2u(unsigned a, unsigned b) {
    __half2 r = __hmax2(*reinterpret_cast<__half2*>(&a), *reinterpret_cast<__half2*>(&b));
    return *reinterpret_cast<unsigned*>(&r);
}
__device__ __forceinline__ int ld_acq_gpu(const int* p) {
    int v; asm volatile("ld.acquire.gpu.s32 %0, [%1];" : "=r"(v) : "l"(p) : "memory");
    return v;
}
__device__ __forceinline__ void st_rel_gpu(int* p, int v) {
    asm volatile("st.release.gpu.s32 [%0], %1;" :: "l"(p), "r"(v) : "memory");
}

#define UBAR(id) asm volatile("bar.sync %0, %1;" :: "r"(id), "r"(128) : "memory")

#define LDMX4(r0, r1, r2, r3, addr)                                            \
    asm volatile("ldmatrix.sync.aligned.m8n8.x4.shared.b16 {%0,%1,%2,%3}, [%4];" \
                 : "=r"(r0), "=r"(r1), "=r"(r2), "=r"(r3) : "r"(addr))

#define MMA16816(c, a, bb0, bb1)                                               \
    asm volatile("mma.sync.aligned.m16n8k16.row.col.f32.f16.f16.f32 "          \
                 "{%0,%1,%2,%3},{%4,%5,%6,%7},{%8,%9},{%0,%1,%2,%3};"          \
                 : "+f"((c)[0]), "+f"((c)[1]), "+f"((c)[2]), "+f"((c)[3])      \
                 : "r"((a)[0]), "r"((a)[1]), "r"((a)[2]), "r"((a)[3]),         \
                   "r"(bb0), "r"(bb1))

// ---------------------------------------------------------------------------
// fill: INF boundary slots of g_cst; INF g_ring; zero flags/xprog; order table.
// ---------------------------------------------------------------------------
__global__ __launch_bounds__(256) void fill_kernel() {
    int cta = blockIdx.x;                       // 256 CTAs, one per (b,w)
    unsigned* p32 = (unsigned*)(g_cst + (size_t)cta * SPAD * 128);
    const int NS = 189 + (SPAD - 1024);
    for (int v = threadIdx.x; v < NS * 64; v += 256) {
        int sr = v >> 6, q = v & 63;
        int s = (sr < 189) ? sr : (1024 + sr - 189);
        p32[(size_t)s * 64 + q] = 0x7C007C00u;
    }
    int fi = cta * 256 + threadIdx.x;
    if (fi < BATCH * NW * 32) g_flag[fi] = 0;
    if (cta < BATCH) {
        unsigned* rr = (unsigned*)(g_ring + cta * RSTR);
        for (int v = threadIdx.x; v < RSTR / 2; v += 256) rr[v] = 0x7C007C00u;
        if (threadIdx.x == 0) g_xprog[cta] = 0;
    }
    if (cta == 0 && threadIdx.x == 0) {
        int idx = 0;
        for (int m = 0; m <= 80; m++)
            for (int w = 0; w < 8; w++) {
                int jt = m - 7 * w;
                if (jt >= 0 && jt < 32) g_pairs[idx++] = (unsigned char)(w * 32 + jt);
            }
    }
}

// ---------------------------------------------------------------------------
// Producer unit: 128 threads, fp16 tensor-core GEMM (m16n8k16), 128x32 tile.
// ---------------------------------------------------------------------------
__device__ void producer_part(const float* __restrict__ A, const float* __restrict__ B,
                              char* __restrict__ base, int barid, int unit, int t128) {
    __half* Ah  = (__half*)base;                 // [128][72]
    __half* Bh  = (__half*)(base + BH_OFF);      // [32][72]
    float* na_s = (float*)(base + NA_OFF);       // [128]
    float* nb4  = (float*)(base + NB_OFF);       // [4][32]
    const int wq = t128 >> 5, l = t128 & 31;
    const unsigned sBase = (unsigned)__cvta_generic_to_shared(base);
    const unsigned sAh = sBase, sBh = sBase + BH_OFF;

    const int m0 = 32 * wq;
    const unsigned ahAddr = sAh + (unsigned)(((m0 + (l & 15)) * 72 + (l >> 4) * 8) * 2);
    const unsigned bhAddr = sBh + (unsigned)((((l & 15)) * 72 + (l >> 4) * 8) * 2);

    for (int p = unit; p < NTILES; p += NUNITS) {
        int pr = g_pairs[p >> 5];
        int b = p & 31, w = pr >> 5, jt = pr & 31;
        int j0 = jt * 32;

        {   // A rows + fp16 convert + norm
            const float4* Ar = (const float4*)(A + ((size_t)b * T + w * 128 + t128) * DIM);
            float na = 0.f;
            uint2* dst = (uint2*)(Ah + t128 * 72);
#pragma unroll
            for (int kq = 0; kq < 16; kq++) {
                float4 v = Ar[kq];
                na += v.x * v.x + v.y * v.y + v.z * v.z + v.w * v.w;
                __half2 h0 = __floats2half2_rn(v.x, v.y);
                __half2 h1 = __floats2half2_rn(v.z, v.w);
                uint2 u; u.x = *(unsigned*)&h0; u.y = *(unsigned*)&h1;
                dst[kq] = u;
            }
            na_s[t128] = na;
        }
        {   // B rows + convert + partial norms
            int j = t128 & 31, q4 = t128 >> 5;
            const float4* Br = (const float4*)(B + ((size_t)b * T + j0 + j) * DIM) + q4 * 4;
            float nb = 0.f;
            uint2* dst = (uint2*)(Bh + j * 72 + q4 * 16);
#pragma unroll
            for (int kk = 0; kk < 4; kk++) {
                float4 v = Br[kk];
                nb += v.x * v.x + v.y * v.y + v.z * v.z + v.w * v.w;
                __half2 h0 = __floats2half2_rn(v.x, v.y);
                __half2 h1 = __floats2half2_rn(v.z, v.w);
                uint2 u; u.x = *(unsigned*)&h0; u.y = *(unsigned*)&h1;
                dst[kk] = u;
            }
            nb4[q4 * 32 + j] = nb;
        }
        UBAR(barid);

        if (t128 < 32)
            nb4[t128] += nb4[32 + t128] + nb4[64 + t128] + nb4[96 + t128];

        float acc[2][4][4];
#pragma unroll
        for (int mi = 0; mi < 2; mi++)
#pragma unroll
            for (int nj = 0; nj < 4; nj++)
#pragma unroll
                for (int q = 0; q < 4; q++) acc[mi][nj][q] = 0.f;

#pragma unroll
        for (int kk = 0; kk < 4; kk++) {
            unsigned a0[4], a1[4], b0[4], b1[4];
            LDMX4(a0[0], a0[1], a0[2], a0[3], ahAddr + kk * 32);
            LDMX4(a1[0], a1[1], a1[2], a1[3], ahAddr + 2304 + kk * 32);
            LDMX4(b0[0], b0[1], b0[2], b0[3], bhAddr + kk * 32);
            LDMX4(b1[0], b1[1], b1[2], b1[3], bhAddr + 2304 + kk * 32);
            MMA16816(acc[0][0], a0, b0[0], b0[2]);
            MMA16816(acc[0][1], a0, b0[1], b0[3]);
            MMA16816(acc[0][2], a0, b1[0], b1[2]);
            MMA16816(acc[0][3], a0, b1[1], b1[3]);
            MMA16816(acc[1][0], a1, b0[0], b0[2]);
            MMA16816(acc[1][1], a1, b0[1], b0[3]);
            MMA16816(acc[1][2], a1, b1[0], b1[2]);
            MMA16816(acc[1][3], a1, b1[1], b1[3]);
        }
        UBAR(barid);                 // Ah reads done; reuse as Ch

        __half* Ch = (__half*)base;  // [128][34]
        {
            const int cb = 2 * (l & 3);
#pragma unroll
            for (int mi = 0; mi < 2; mi++) {
                int r = m0 + 16 * mi + (l >> 2);
                float na0 = na_s[r], na8 = na_s[r + 8];
#pragma unroll
                for (int nj = 0; nj < 4; nj++) {
                    int c0 = 8 * nj + cb;
                    float nb0 = nb4[c0], nb1 = nb4[c0 + 1];
                    float s00 = fmaxf(na0 + nb0 - 2.f * acc[mi][nj][0], 1e-12f);
                    float s01 = fmaxf(na0 + nb1 - 2.f * acc[mi][nj][1], 1e-12f);
                    float s10 = fmaxf(na8 + nb0 - 2.f * acc[mi][nj][2], 1e-12f);
                    float s11 = fmaxf(na8 + nb1 - 2.f * acc[mi][nj][3], 1e-12f);
                    __half2 h0 = __floats2half2_rn(s00, s01);
                    __half2 h1 = __floats2half2_rn(s10, s11);
                    *(unsigned*)&Ch[r * 34 + c0] = *(unsigned*)&h0;
                    *(unsigned*)&Ch[(r + 8) * 34 + c0] = *(unsigned*)&h1;
                }
            }
        }
        UBAR(barid);

        // Skewed emit: slot s = j + phi(i); sr = s - j0 in [0, SRMAX).
        size_t sbase = ((size_t)(b * NW + w) * SPAD + j0) * 128;
#pragma unroll 1
        for (int it = 0; it < 56; it++) {
            int sr = it * 4 + wq;
            if (sr < SRMAX) {
                int aq = sr / 6, bq = sr - 6 * aq;
                int ihi = 4 * aq + (bq < 3 ? bq : 3);
                if (ihi > 127) ihi = 127;
                int i = ihi - 31 + l;
                if (i >= 0) {
                    int jr = sr - (6 * (i >> 2) + (i & 3));
                    if (jr >= 0 && jr < 32)
                        g_cst[sbase + (size_t)sr * 128 + i] = Ch[i * 34 + jr];
                }
            }
        }
        __threadfence();
        UBAR(barid);
        if (t128 == 0)
            ((volatile int*)g_flag)[(b * NW + w) * 32 + jt] = 1;
    }
}

// ---------------------------------------------------------------------------
// DP part: batch split across 2 CTAs (4 warps each, 1 warp/SMSP).
// half h=0: global strips 0..3; h=1: strips 4..7. The w3->w4 handoff goes
// through g_ring (L2): producer lane31 st.global.u16 per step at index s-190;
// consumer at step sigma reads ring[sigma], batched 4xLDG.128 per 32 steps.
// ---------------------------------------------------------------------------
__device__ void dp_part(int b, int h, char* smem) {
    unsigned short* hand = (unsigned short*)smem;     // 5 rows x HANDW
    int* progress = (int*)(smem + DP_PROG_OFF);
    const int tid = threadIdx.x, w = tid >> 5, lane = tid & 31;
    const int wg = 4 * h + w;

    for (int v = tid; v < 5 * HANDW / 2; v += 128)
        ((unsigned*)hand)[v] = 0x7C007C00u;
    if (lane == 0) progress[w] = 0;
    asm volatile("bar.sync 6, 128;" ::: "memory");

    const bool ringC = (h == 1) && (w == 0);          // ring consumer
    const bool ringP = (h == 0) && (w == 3);          // ring producer

    // local consumers: hrow = hand[w-1]; w0 reads dummy INF row 4
    const unsigned short* hrow = &hand[((w == 0) ? 4 : (w - 1)) * HANDW];
    unsigned wrow;   // local publish: +s*2 -> hand[w][s-189]
    {
        unsigned base;
        asm("{ .reg .u64 t; cvta.to.shared.u64 t, %1; cvt.u32.u64 %0, t; }"
            : "=r"(base) : "l"(&hand[w * HANDW]));
        wrow = base - 378u;
    }
    const __half* ringb = g_ring + b * RSTR;
    unsigned long long wring = (unsigned long long)ringb - 380ull;  // +s*2 -> ring[s-190]

    const int fbase = (b * NW + wg) * 32;
    int done = 0;
    while (ld_acq_gpu(&g_flag[fbase]) == 0) __nanosleep(128);
    done = 1;

    const __half* cp = g_cst + (size_t)(b * NW + wg) * SPAD * 128 + lane * 4;
    uint2 fA[16], fB[16];
#pragma unroll
    for (int q = 0; q < 16; q++) fA[q] = *(const uint2*)(cp + (size_t)q * 128);
#pragma unroll
    for (int q = 0; q < 16; q++) fB[q] = *(const uint2*)(cp + (size_t)(16 + q) * 128);

    const unsigned INF2 = 0x7C007C00u;
    unsigned A = INF2, B = INF2, upAp = INF2, upBp = INF2;
    unsigned sh0 = INF2, sh1 = INF2;
    unsigned hv0 = INF2, hv1 = INF2, hv2 = INF2;
    unsigned qq[16];                                   // ring chunk buffer (lane0)
#pragma unroll
    for (int q = 0; q < 16; q++) qq[q] = INF2;
    const bool isl0 = (lane == 0);
    const bool fix0 = (h == 0) && (w == 0) && isl0;
    const unsigned p31 = (lane == 31) ? 1u : 0u;
    const unsigned pSTS = p31 & (ringP ? 0u : 1u);
    const unsigned pSTG = p31 & (ringP ? 1u : 0u);
    const __half* cq = cp;

    // RINGV(kk2): ring value for in-chunk step kk2, packed into high half
#define RINGV(kk2) (((kk2) & 1) ? (qq[(kk2) >> 1] & 0xFFFF0000u) : (qq[(kk2) >> 1] << 16))

#define DP_STEP(kk, KOFF, F, ROFF, FIRST)                                      \
    {                                                                          \
        const int s = sbase + (kk);                                            \
        uint2 cw = F[kk];                                                      \
        F[kk] = *(const uint2*)(cq + (size_t)((kk) + (ROFF)) * 128);           \
        unsigned hvsel = ringC ? RINGV((KOFF) + (kk)) : hv0;                   \
        unsigned shu = isl0 ? hvsel : sh0;                                     \
        unsigned upA = __byte_perm(shu, A, 0x5432);                            \
        unsigned upB = __byte_perm(A, B, 0x5432);                              \
        unsigned nA = hmax2u(cw.x, hmin2u(hmin2u(upA, upAp), A));              \
        unsigned nB = hmax2u(cw.y, hmin2u(hmin2u(upB, upBp), B));              \
        if ((FIRST) && (kk) == 0) {                                            \
            if (fix0) nA = (nA & 0xFFFF0000u) | (cw.x & 0xFFFFu);              \
        }                                                                      \
        unsigned prs = pSTS & (unsigned)(s >= 189);                            \
        asm volatile(                                                          \
            "{ .reg .pred p; setp.ne.u32 p, %0, 0; @p st.shared.u16 [%1], %2; }" \
            :: "r"(prs), "r"(wrow + (unsigned)s * 2),                          \
               "h"((unsigned short)(nB >> 16)));                               \
        unsigned prg = pSTG & (unsigned)(s >= 190);                            \
        asm volatile(                                                          \
            "{ .reg .pred p; setp.ne.u32 p, %0, 0; @p st.global.u16 [%1], %2; }" \
            :: "r"(prg), "l"(wring + (unsigned long long)s * 2),               \
               "h"((unsigned short)(nB >> 16)));                               \
        unsigned shn = __shfl_up_sync(0xffffffffu, B, 1);                      \
        sh0 = sh1; sh1 = shn;                                                  \
        upAp = upA; upBp = upB;                                                \
        A = nA; B = nB;                                                        \
        hv0 = hv1; hv1 = hv2;                                                  \
        hv2 = ((unsigned)hrow[s + 3]) << 16;                                   \
    }

    for (int td = 0; td < NCH / 2; td++) {
        {   // gate on producer tiles for this strip
            int need = td + 2; if (need > 32) need = 32;
            while (done < need) {
                if (ld_acq_gpu(&g_flag[fbase + done]) != 0) done++;
                else __nanosleep(64);
            }
        }
        int need = 2 * td + 14; if (need > NCH) need = NCH;
        if (w) {                                       // local handoff gate
            while (((volatile int*)progress)[w - 1] < need) __nanosleep(32);
            __threadfence_block();
        } else if (ringC) {                            // cross-CTA gate
            while (ld_acq_gpu(&g_xprog[b]) < need) __nanosleep(32);
        }
        if (ringC && isl0) {                           // batched ring fetch
            const uint4* rp = (const uint4*)(ringb + 32 * td);
            uint4 q0 = rp[0], q1 = rp[1], q2 = rp[2], q3 = rp[3];
            qq[0] = q0.x; qq[1] = q0.y; qq[2] = q0.z; qq[3] = q0.w;
            qq[4] = q1.x; qq[5] = q1.y; qq[6] = q1.z; qq[7] = q1.w;
            qq[8] = q2.x; qq[9] = q2.y; qq[10] = q2.z; qq[11] = q2.w;
            qq[12] = q3.x; qq[13] = q3.y; qq[14] = q3.z; qq[15] = q3.w;
        }
        if (td == 0) {
            hv0 = ((unsigned)hrow[0]) << 16;
            hv1 = ((unsigned)hrow[1]) << 16;
            hv2 = ((unsigned)hrow[2]) << 16;
        }
        {
            const int sbase = 32 * td;
#pragma unroll
            for (int kk = 0; kk < 16; kk++) DP_STEP(kk, 0, fA, 32, (td == 0))
        }
        __syncwarp();
        __threadfence_block();
        if (lane == 0) ((volatile int*)progress)[w] = 2 * td + 1;
        if (ringP && lane == 31) st_rel_gpu(&g_xprog[b], 2 * td + 1);
        {
            const int sbase = 32 * td + 16;
#pragma unroll
            for (int kk = 0; kk < 16; kk++) DP_STEP(kk, 16, fB, 48, false)
        }
        __syncwarp();
        __threadfence_block();
        if (lane == 0) ((volatile int*)progress)[w] = 2 * td + 2;
        if (ringP && lane == 31) st_rel_gpu(&g_xprog[b], 2 * td + 2);
        cq += 32 * 128;
    }
#undef DP_STEP
#undef RINGV

    asm volatile("bar.sync 6, 128;" ::: "memory");
    if (h == 1 && tid == 0)
        g_dists[b] = sqrtf(__half2float(__ushort_as_half(hand[3 * HANDW + 1023])));
}

// ---------------------------------------------------------------------------
// Fused persistent kernel, 148 CTAs (all wave-1 resident).
//   CTA 0..63:  DP half-CTAs (batch = cta>>1, half = cta&1), 4 warps active.
//   CTA 64..147: 3 tensor-core producer units each.
// ---------------------------------------------------------------------------
__global__ void __launch_bounds__(384, 1) fused_kernel(const float* __restrict__ A,
                                                       const float* __restrict__ B) {
    extern __shared__ char smem[];
    const int cta = blockIdx.x, tid = threadIdx.x;
    if (cta < 2 * BATCH) {
        if (tid < 128) dp_part(cta >> 1, cta & 1, smem);
        return;
    }
    int ul = tid >> 7;
    producer_part(A, B, smem + ul * UNIT_BYTES, 1 + ul,
                  (cta - 2 * BATCH) * 3 + ul, tid & 127);
}

// ---------------------------------------------------------------------------
__global__ void finish_kernel(float* __restrict__ out) {
    int t = threadIdx.x;
    float v = g_dists[t];
#pragma unroll
    for (int o = 16; o; o >>= 1) v += __shfl_xor_sync(0xffffffffu, v, o);
    if (t == 0) out[0] = v * (1.0f / BATCH);
}

extern "C" void kernel_launch(void* const* d_in, const int* in_sizes, int n_in,
                              void* d_out, int out_size) {
    const float* pred = (const float*)d_in[0];
    const float* targ = (const float*)d_in[1];
    cudaFuncSetAttribute(fused_kernel, cudaFuncAttributeMaxDynamicSharedMemorySize, SMEM_DYN);
    fill_kernel<<<BATCH * NW, 256>>>();
    fused_kernel<<<148, 384, SMEM_DYN>>>(pred, targ);
    finish_kernel<<<1, 32>>>((float*)d_out);
}

// round 13
// speedup vs baseline: 1.4774x; 1.4774x over previous
#include <cuda_runtime.h>
#include <cuda_fp16.h>
#include <math.h>

#define BATCH 32
#define T     1024
#define DIM   64
#define NW    8                 // DP strips per batch (128 rows each)
#define NCH   76                // chunks of 16 steps: 1216 steps
#define SPAD  1248              // NCH*16 + 32 FIFO pad
#define HANDW 1220              // handoff row width (halves)
#define SRMAX 221               // epilogue s-rows per tile
#define NUNITS 348              // producer units: 116 CTAs * 3
#define NTILES 8192             // 32 b * 8 w * 32 jt
#define HAND_BYTES ((NW + 1) * HANDW * 2)     // 21960
#define PROG_OFF   HAND_BYTES
// producer unit: Ah[128][72]h | Bh[32][72]h | na[128]f | nb[32]f
#define BH_OFF     18432
#define NA_OFF     23040
#define NB_OFF     23552
#define UNIT_BYTES 24064
#define SMEM_DYN   (3 * UNIT_BYTES)           // 72192

// fp16 cost^2, skew-slotted: g_cst[((b*NW+w)*SPAD + s)*128 + i] holds
// cost[128w+i][s - phi(i)], phi(i) = 6*(i>>2) + (i&3). Invalid = +INF.
__device__ __half g_cst[(size_t)BATCH * NW * SPAD * 128];
__device__ float g_dists[BATCH];
__device__ int   g_flag[BATCH * NW * 32];
__device__ unsigned char g_pairs[256];
__device__ unsigned char g_ihi[224];          // emit table: max i with phi(i)<=sr

__device__ __forceinline__ unsigned hmin2u(unsigned a, unsigned b) {
    __half2 r = __hmin2(*reinterpret_cast<__half2*>(&a), *reinterpret_cast<__half2*>(&b));
    return *reinterpret_cast<unsigned*>(&r);
}
__device__ __forceinline__ unsigned hmax2u(unsigned a, unsigned b) {
    __half2 r = __hmax2(*reinterpret_cast<__half2*>(&a), *reinterpret_cast<__half2*>(&b));
    return *reinterpret_cast<unsigned*>(&r);
}
__device__ __forceinline__ int ld_acq_gpu(const int* p) {
    int v; asm volatile("ld.acquire.gpu.s32 %0, [%1];" : "=r"(v) : "l"(p) : "memory");
    return v;
}

#define UBAR(id) asm volatile("bar.sync %0, %1;" :: "r"(id), "r"(128) : "memory")

#define LDMX4(r0, r1, r2, r3, addr)                                            \
    asm volatile("ldmatrix.sync.aligned.m8n8.x4.shared.b16 {%0,%1,%2,%3}, [%4];" \
                 : "=r"(r0), "=r"(r1), "=r"(r2), "=r"(r3) : "r"(addr))

#define MMA16816(c, a, bb0, bb1)                                               \
    asm volatile("mma.sync.aligned.m16n8k16.row.col.f32.f16.f16.f32 "          \
                 "{%0,%1,%2,%3},{%4,%5,%6,%7},{%8,%9},{%0,%1,%2,%3};"          \
                 : "+f"((c)[0]), "+f"((c)[1]), "+f"((c)[2]), "+f"((c)[3])      \
                 : "r"((a)[0]), "r"((a)[1]), "r"((a)[2]), "r"((a)[3]),         \
                   "r"(bb0), "r"(bb1))

// ---------------------------------------------------------------------------
// fill: INF boundary slots; zero flags; order table; emit table.
// ---------------------------------------------------------------------------
__global__ __launch_bounds__(256) void fill_kernel() {
    int cta = blockIdx.x;                       // 256 CTAs, one per (b,w)
    unsigned* p32 = (unsigned*)(g_cst + (size_t)cta * SPAD * 128);
    const int NS = 189 + (SPAD - 1024);
    for (int v = threadIdx.x; v < NS * 64; v += 256) {
        int sr = v >> 6, q = v & 63;
        int s = (sr < 189) ? sr : (1024 + sr - 189);
        p32[(size_t)s * 64 + q] = 0x7C007C00u;
    }
    int fi = cta * 256 + threadIdx.x;
    if (fi < BATCH * NW * 32) g_flag[fi] = 0;
    if (cta == 0 && threadIdx.x == 0) {
        int idx = 0;
        for (int m = 0; m <= 80; m++)
            for (int w = 0; w < 8; w++) {
                int jt = m - 7 * w;
                if (jt >= 0 && jt < 32) g_pairs[idx++] = (unsigned char)(w * 32 + jt);
            }
    }
    if (cta == 1 && threadIdx.x < 224) {
        int sr = threadIdx.x;
        int aq = sr / 6, bq = sr - 6 * aq;
        int ihi = 4 * aq + (bq < 3 ? bq : 3);
        g_ihi[sr] = (unsigned char)(ihi > 127 ? 127 : ihi);
    }
}

// ---------------------------------------------------------------------------
// Producer unit: 128 threads, fp16 tensor-core GEMM (m16n8k16), 128x32 tile.
// Coalesced v-loop loads (512B/warp/LDG) with width-16 shfl norm reduction;
// table-driven skewed emit.
// ---------------------------------------------------------------------------
__device__ void producer_part(const float* __restrict__ A, const float* __restrict__ B,
                              char* __restrict__ base, int barid, int unit, int t128) {
    __half* Ah  = (__half*)base;                 // [128][72]
    __half* Bh  = (__half*)(base + BH_OFF);      // [32][72]
    float* na_s = (float*)(base + NA_OFF);       // [128]
    float* nb_s = (float*)(base + NB_OFF);       // [32]
    const int wq = t128 >> 5, l = t128 & 31;
    const int r0 = t128 >> 4, kq = t128 & 15;
    const unsigned sBase = (unsigned)__cvta_generic_to_shared(base);
    const unsigned sAh = sBase, sBh = sBase + BH_OFF;

    const int m0 = 32 * wq;
    const unsigned ahAddr = sAh + (unsigned)(((m0 + (l & 15)) * 72 + (l >> 4) * 8) * 2);
    const unsigned bhAddr = sBh + (unsigned)((((l & 15)) * 72 + (l >> 4) * 8) * 2);

    for (int p = unit; p < NTILES; p += NUNITS) {
        int pr = g_pairs[p >> 5];
        int b = p & 31, w = pr >> 5, jt = pr & 31;
        int j0 = jt * 32;

        // A tile: coalesced (warp = 512B contiguous), norm via shfl width-16
        {
            const float4* Ar = (const float4*)(A + ((size_t)b * T + w * 128) * DIM);
#pragma unroll
            for (int it = 0; it < 16; it++) {
                int row = r0 + it * 8;
                float4 x = Ar[row * 16 + kq];
                float part = x.x * x.x + x.y * x.y + x.z * x.z + x.w * x.w;
                part += __shfl_xor_sync(0xffffffffu, part, 1);
                part += __shfl_xor_sync(0xffffffffu, part, 2);
                part += __shfl_xor_sync(0xffffffffu, part, 4);
                part += __shfl_xor_sync(0xffffffffu, part, 8);
                if (kq == 0) na_s[row] = part;
                __half2 h0 = __floats2half2_rn(x.x, x.y);
                __half2 h1 = __floats2half2_rn(x.z, x.w);
                uint2 u; u.x = *(unsigned*)&h0; u.y = *(unsigned*)&h1;
                *(uint2*)(Ah + row * 72 + kq * 4) = u;
            }
        }
        // B tile: same pattern, 4 iterations
        {
            const float4* Br = (const float4*)(B + ((size_t)b * T + j0) * DIM);
#pragma unroll
            for (int it = 0; it < 4; it++) {
                int row = r0 + it * 8;
                float4 x = Br[row * 16 + kq];
                float part = x.x * x.x + x.y * x.y + x.z * x.z + x.w * x.w;
                part += __shfl_xor_sync(0xffffffffu, part, 1);
                part += __shfl_xor_sync(0xffffffffu, part, 2);
                part += __shfl_xor_sync(0xffffffffu, part, 4);
                part += __shfl_xor_sync(0xffffffffu, part, 8);
                if (kq == 0) nb_s[row] = part;
                __half2 h0 = __floats2half2_rn(x.x, x.y);
                __half2 h1 = __floats2half2_rn(x.z, x.w);
                uint2 u; u.x = *(unsigned*)&h0; u.y = *(unsigned*)&h1;
                *(uint2*)(Bh + row * 72 + kq * 4) = u;
            }
        }
        UBAR(barid);

        float acc[2][4][4];
#pragma unroll
        for (int mi = 0; mi < 2; mi++)
#pragma unroll
            for (int nj = 0; nj < 4; nj++)
#pragma unroll
                for (int q = 0; q < 4; q++) acc[mi][nj][q] = 0.f;

#pragma unroll
        for (int kk = 0; kk < 4; kk++) {
            unsigned a0[4], a1[4], b0[4], b1[4];
            LDMX4(a0[0], a0[1], a0[2], a0[3], ahAddr + kk * 32);
            LDMX4(a1[0], a1[1], a1[2], a1[3], ahAddr + 2304 + kk * 32);
            LDMX4(b0[0], b0[1], b0[2], b0[3], bhAddr + kk * 32);
            LDMX4(b1[0], b1[1], b1[2], b1[3], bhAddr + 2304 + kk * 32);
            MMA16816(acc[0][0], a0, b0[0], b0[2]);
            MMA16816(acc[0][1], a0, b0[1], b0[3]);
            MMA16816(acc[0][2], a0, b1[0], b1[2]);
            MMA16816(acc[0][3], a0, b1[1], b1[3]);
            MMA16816(acc[1][0], a1, b0[0], b0[2]);
            MMA16816(acc[1][1], a1, b0[1], b0[3]);
            MMA16816(acc[1][2], a1, b1[0], b1[2]);
            MMA16816(acc[1][3], a1, b1[1], b1[3]);
        }
        UBAR(barid);                 // Ah reads done; reuse as Ch

        __half* Ch = (__half*)base;  // [128][34]
        {
            const int cb = 2 * (l & 3);
#pragma unroll
            for (int mi = 0; mi < 2; mi++) {
                int r = m0 + 16 * mi + (l >> 2);
                float na0 = na_s[r], na8 = na_s[r + 8];
#pragma unroll
                for (int nj = 0; nj < 4; nj++) {
                    int c0 = 8 * nj + cb;
                    float nb0 = nb_s[c0], nb1 = nb_s[c0 + 1];
                    float s00 = fmaxf(na0 + nb0 - 2.f * acc[mi][nj][0], 1e-12f);
                    float s01 = fmaxf(na0 + nb1 - 2.f * acc[mi][nj][1], 1e-12f);
                    float s10 = fmaxf(na8 + nb0 - 2.f * acc[mi][nj][2], 1e-12f);
                    float s11 = fmaxf(na8 + nb1 - 2.f * acc[mi][nj][3], 1e-12f);
                    __half2 h0 = __floats2half2_rn(s00, s01);
                    __half2 h1 = __floats2half2_rn(s10, s11);
                    *(unsigned*)&Ch[r * 34 + c0] = *(unsigned*)&h0;
                    *(unsigned*)&Ch[(r + 8) * 34 + c0] = *(unsigned*)&h1;
                }
            }
        }
        UBAR(barid);

        // Table-driven skewed emit: slot s = j + phi(i); sr = s - j0.
        size_t sbase = ((size_t)(b * NW + w) * SPAD + j0) * 128;
#pragma unroll 1
        for (int it = 0; it < 56; it++) {
            int sr = it * 4 + wq;
            if (sr < SRMAX) {
                int ihi = __ldg(&g_ihi[sr]);
                int i = ihi - 31 + l;
                int jr = sr - (6 * (i >> 2) + (i & 3));
                if (i >= 0 && jr >= 0 && jr < 32)
                    g_cst[sbase + (size_t)sr * 128 + i] = Ch[i * 34 + jr];
            }
        }
        __threadfence();
        UBAR(barid);
        if (t128 == 0)
            ((volatile int*)g_flag)[(b * NW + w) * 32 + jt] = 1;
    }
}

// ---------------------------------------------------------------------------
// DP part: sole occupant of its CTA/SM. E=2-skew systolic engine; chunks
// gated on cumulative tile flags. (Proven R11 engine, unchanged.)
// ---------------------------------------------------------------------------
__device__ void dp_part(int b, char* smem) {
    unsigned short* hand = (unsigned short*)smem;
    int* progress = (int*)(smem + PROG_OFF);
    const int tid = threadIdx.x, w = tid >> 5, lane = tid & 31;

    for (int v = tid; v < (NW + 1) * HANDW / 2; v += 256)
        ((unsigned*)hand)[v] = 0x7C007C00u;
    if (lane == 0) progress[w] = 0;
    asm volatile("bar.sync 5, 256;" ::: "memory");

    const unsigned short* hrow = &hand[((w == 0) ? NW : (w - 1)) * HANDW];
    unsigned wrow;   // smem addr; +s*2 -> hand[w][s-189]
    {
        unsigned base;
        asm("{ .reg .u64 t; cvta.to.shared.u64 t, %1; cvt.u32.u64 %0, t; }"
            : "=r"(base) : "l"(&hand[w * HANDW]));
        wrow = base - 378u;
    }

    const int fbase = (b * NW + w) * 32;
    int done = 0;
    while (ld_acq_gpu(&g_flag[fbase]) == 0) __nanosleep(128);
    done = 1;

    const __half* cp = g_cst + (size_t)(b * NW + w) * SPAD * 128 + lane * 4;
    uint2 fA[16], fB[16];
#pragma unroll
    for (int q = 0; q < 16; q++) fA[q] = *(const uint2*)(cp + (size_t)q * 128);
#pragma unroll
    for (int q = 0; q < 16; q++) fB[q] = *(const uint2*)(cp + (size_t)(16 + q) * 128);

    const unsigned INF2 = 0x7C007C00u;
    unsigned A = INF2, B = INF2, upAp = INF2, upBp = INF2;
    unsigned sh0 = INF2, sh1 = INF2;
    unsigned hv0 = INF2, hv1 = INF2, hv2 = INF2;
    const bool isl0 = (lane == 0);
    const bool fix0 = (w == 0) && isl0;
    const unsigned p31 = (lane == 31) ? 1u : 0u;
    const __half* cq = cp;

#define DP_STEP(kk, F, ROFF, FIRST)                                            \
    {                                                                          \
        const int s = sbase + (kk);                                            \
        uint2 cw = F[kk];                                                      \
        F[kk] = *(const uint2*)(cq + (size_t)((kk) + (ROFF)) * 128);           \
        unsigned shu = isl0 ? hv0 : sh0;                                       \
        unsigned upA = __byte_perm(shu, A, 0x5432);                            \
        unsigned upB = __byte_perm(A, B, 0x5432);                              \
        unsigned nA = hmax2u(cw.x, hmin2u(hmin2u(upA, upAp), A));              \
        unsigned nB = hmax2u(cw.y, hmin2u(hmin2u(upB, upBp), B));              \
        if ((FIRST) && (kk) == 0) {                                            \
            if (fix0) nA = (nA & 0xFFFF0000u) | (cw.x & 0xFFFFu);              \
        }                                                                      \
        unsigned pr = p31 & (unsigned)(s >= 189);                              \
        asm volatile(                                                          \
            "{ .reg .pred p; setp.ne.u32 p, %0, 0; @p st.shared.u16 [%1], %2; }" \
            :: "r"(pr), "r"(wrow + (unsigned)s * 2),                           \
               "h"((unsigned short)(nB >> 16)));                               \
        unsigned shn = __shfl_up_sync(0xffffffffu, B, 1);                      \
        sh0 = sh1; sh1 = shn;                                                  \
        upAp = upA; upBp = upB;                                                \
        A = nA; B = nB;                                                        \
        hv0 = hv1; hv1 = hv2;                                                  \
        hv2 = ((unsigned)hrow[s + 3]) << 16;                                   \
    }

    for (int td = 0; td < NCH / 2; td++) {
        {   // gate: chunk td refills read slots <= 32*td+63 -> tiles <= td+1
            int need = td + 2; if (need > 32) need = 32;
            while (done < need) {
                if (ld_acq_gpu(&g_flag[fbase + done]) != 0) done++;
                else __nanosleep(64);
            }
        }
        if (w) {
            int need = 2 * td + 14; if (need > NCH) need = NCH;
            while (((volatile int*)progress)[w - 1] < need) __nanosleep(32);
            __threadfence_block();
        }
        if (td == 0) {
            hv0 = ((unsigned)hrow[0]) << 16;
            hv1 = ((unsigned)hrow[1]) << 16;
            hv2 = ((unsigned)hrow[2]) << 16;
        }
        {
            const int sbase = 32 * td;
#pragma unroll
            for (int kk = 0; kk < 16; kk++) DP_STEP(kk, fA, 32, (td == 0))
        }
        __syncwarp();
        __threadfence_block();
        if (lane == 0) ((volatile int*)progress)[w] = 2 * td + 1;
        {
            const int sbase = 32 * td + 16;
#pragma unroll
            for (int kk = 0; kk < 16; kk++) DP_STEP(kk, fB, 48, false)
        }
        __syncwarp();
        __threadfence_block();
        if (lane == 0) ((volatile int*)progress)[w] = 2 * td + 2;
        cq += 32 * 128;
    }
#undef DP_STEP

    asm volatile("bar.sync 5, 256;" ::: "memory");
    if (tid == 0)
        g_dists[b] = sqrtf(__half2float(__ushort_as_half(hand[7 * HANDW + 1023])));
}

// ---------------------------------------------------------------------------
// Fused persistent kernel, 148 CTAs (all wave-1 resident).
//   CTA 0..31:  DP warps only (batch = blockIdx).
//   CTA 32..147: 3 tensor-core producer units.
// ---------------------------------------------------------------------------
__global__ void __launch_bounds__(384, 1) fused_kernel(const float* __restrict__ A,
                                                       const float* __restrict__ B) {
    extern __shared__ char smem[];
    const int cta = blockIdx.x, tid = threadIdx.x;
    if (cta < BATCH) {
        if (tid < 256) dp_part(cta, smem);
        return;
    }
    int ul = tid >> 7;
    producer_part(A, B, smem + ul * UNIT_BYTES, 1 + ul,
                  (cta - BATCH) * 3 + ul, tid & 127);
}

// ---------------------------------------------------------------------------
__global__ void finish_kernel(float* __restrict__ out) {
    int t = threadIdx.x;
    float v = g_dists[t];
#pragma unroll
    for (int o = 16; o; o >>= 1) v += __shfl_xor_sync(0xffffffffu, v, o);
    if (t == 0) out[0] = v * (1.0f / BATCH);
}

extern "C" void kernel_launch(void* const* d_in, const int* in_sizes, int n_in,
                              void* d_out, int out_size) {
    const float* pred = (const float*)d_in[0];
    const float* targ = (const float*)d_in[1];
    cudaFuncSetAttribute(fused_kernel, cudaFuncAttributeMaxDynamicSharedMemorySize, SMEM_DYN);
    fill_kernel<<<BATCH * NW, 256>>>();
    fused_kernel<<<148, 384, SMEM_DYN>>>(pred, targ);
    finish_kernel<<<1, 32>>>((float*)d_out);
}